// round 5
// baseline (speedup 1.0000x reference)
#include <cuda_runtime.h>
#include <cuda_fp16.h>
#include <mma.h>
#include <math.h>

using namespace nvcuda;

#define NN 50000
#define EE 400000
#define GG 64
#define FIN 16
#define HID 128
#define HEADS 4
#define C1 512   // HEADS*HID
#define MAXD 64

#define SCAN_NB 196          // ceil(50000/256)
#define SCAN_PAD (SCAN_NB*256)

#define A1_NODES 64
#define A1_GRID ((NN + A1_NODES - 1) / A1_NODES)

// ---------------- scratch (static device memory; no allocs) ----------------
__device__ __half   g_out1h[NN * C1];     // layer1 agg (fp16)   51.2 MB
__device__ __half   g_h2h[NN * HID];      // fp16                12.8 MB
__device__ __half   g_out2h[NN * HID];    // fp16                12.8 MB
__device__ float    g_as1[NN * HEADS], g_ad1[NN * HEADS];
__device__ float    g_as2[NN], g_ad2[NN];
__device__ float    g_Ws1[FIN * HEADS], g_Wd1[FIN * HEADS];
__device__ float    g_pool[GG * HID];
__device__ float    g_cnt[GG];
// CSR by destination
__device__ int      g_deg[SCAN_PAD];
__device__ int      g_off[SCAN_PAD + 1];
__device__ int      g_cur[NN];
__device__ int      g_part[SCAN_NB];
__device__ int      g_pref[SCAN_NB];
__device__ int      g_csr_src[EE];

// ---------------- helpers ----------------
__device__ __forceinline__ float leaky(float x) { return x > 0.f ? x : 0.2f * x; }
__device__ __forceinline__ float eluf(float x)  { return x > 0.f ? x : expm1f(x); }

__device__ __forceinline__ float4 h4_to_f4(uint2 u) {
    __half2 a = *(__half2*)&u.x, b = *(__half2*)&u.y;
    float2 fa = __half22float2(a), fb = __half22float2(b);
    return make_float4(fa.x, fa.y, fb.x, fb.y);
}
__device__ __forceinline__ uint2 f4_to_h4(float4 v) {
    __half2 a = __floats2half2_rn(v.x, v.y), b = __floats2half2_rn(v.z, v.w);
    uint2 u; u.x = *(unsigned*)&a; u.y = *(unsigned*)&b; return u;
}

// ---------------- K0: fold layer1 attention vectors into W1, zero pool ----------------
__global__ void k_prep(const float* __restrict__ W1, const float* __restrict__ as1,
                       const float* __restrict__ ad1) {
    int t = threadIdx.x;
    if (t < FIN * HEADS) {
        int k = t >> 2, h = t & 3;
        float s = 0.f, d = 0.f;
        for (int c = 0; c < HID; c++) {
            float w = W1[k * C1 + h * HID + c];
            s += w * as1[h * HID + c];
            d += w * ad1[h * HID + c];
        }
        g_Ws1[t] = s; g_Wd1[t] = d;
    }
    for (int i = t; i < GG * HID; i += blockDim.x) g_pool[i] = 0.f;
    if (t < GG) g_cnt[t] = 0.f;
}

__global__ void k_zero(void) {
    int i = blockIdx.x * blockDim.x + threadIdx.x;
    if (i < SCAN_PAD) g_deg[i] = 0;
}

// ---------------- CSR build ----------------
__global__ void k_hist(const int* __restrict__ dst) {
    int e = blockIdx.x * blockDim.x + threadIdx.x;
    if (e >= EE) return;
    atomicAdd(&g_deg[dst[e]], 1);
}

__global__ void k_scan_block(void) {
    __shared__ int s[256];
    int t = threadIdx.x;
    int i = blockIdx.x * 256 + t;
    int v = g_deg[i];
    s[t] = v;
    __syncthreads();
#pragma unroll
    for (int o = 1; o < 256; o <<= 1) {
        int x = (t >= o) ? s[t - o] : 0;
        __syncthreads();
        s[t] += x;
        __syncthreads();
    }
    g_off[i] = s[t] - v;
    if (t == 255) g_part[blockIdx.x] = s[255];
}

__global__ void k_scan_top(void) {
    __shared__ int s[256];
    int t = threadIdx.x;
    int v = (t < SCAN_NB) ? g_part[t] : 0;
    s[t] = v;
    __syncthreads();
#pragma unroll
    for (int o = 1; o < 256; o <<= 1) {
        int x = (t >= o) ? s[t - o] : 0;
        __syncthreads();
        s[t] += x;
        __syncthreads();
    }
    if (t < SCAN_NB) g_pref[t] = s[t] - v;
}

__global__ void k_scan_add(void) {
    int i = blockIdx.x * blockDim.x + threadIdx.x;
    if (i > SCAN_PAD) return;
    if (i == SCAN_PAD) { g_off[i] = EE; return; }
    int p = g_off[i] + g_pref[i >> 8];
    g_off[i] = p;
    if (i < NN) g_cur[i] = p;
}

__global__ void k_fill(const int* __restrict__ src, const int* __restrict__ dst) {
    int e = blockIdx.x * blockDim.x + threadIdx.x;
    if (e >= EE) return;
    int d = dst[e];
    int p = atomicAdd(&g_cur[d], 1);
    g_csr_src[p] = src[e];
}

// ---------------- K2: per-node attention logits layer1 ----------------
__global__ void k_att1(const float* __restrict__ x) {
    __shared__ float ws[FIN * HEADS], wd[FIN * HEADS];
    int t = threadIdx.x;
    if (t < FIN * HEADS) { ws[t] = g_Ws1[t]; wd[t] = g_Wd1[t]; }
    __syncthreads();
    int n = blockIdx.x * blockDim.x + t;
    if (n >= NN) return;
    float xr[FIN];
    const float4* xp = (const float4*)(x + n * FIN);
#pragma unroll
    for (int i = 0; i < 4; i++) {
        float4 v = xp[i];
        xr[i * 4 + 0] = v.x; xr[i * 4 + 1] = v.y; xr[i * 4 + 2] = v.z; xr[i * 4 + 3] = v.w;
    }
#pragma unroll
    for (int h = 0; h < HEADS; h++) {
        float s = 0.f, d = 0.f;
#pragma unroll
        for (int k = 0; k < FIN; k++) { s += xr[k] * ws[k * 4 + h]; d += xr[k] * wd[k * 4 + h]; }
        g_as1[n * 4 + h] = s;
        g_ad1[n * 4 + h] = d;
    }
}

// ---------------- K3: layer1 aggregate-then-transform ----------------
// Phase 1: warp per node — online softmax stats + aggregate x (16-wide) per head.
// Phase 2: thread per column — z @ W1 with W1 columns register-cached.
#define SZ_LD 68
__global__ __launch_bounds__(512, 1) void k_agg1x(const float* __restrict__ x,
                                                  const float* __restrict__ W1) {
    __shared__ float sz[A1_NODES][SZ_LD];   // [node][h*16+k], padded
    int t = threadIdx.x;
    int warp = t >> 5, lane = t & 31;
    int n0 = blockIdx.x * A1_NODES;

    // ---- phase 1 ----
    for (int i = warp; i < A1_NODES; i += 16) {
        int n = n0 + i;
        if (n >= NN) break;
        int p0 = g_off[n], deg = g_off[n + 1] - p0;
        float4 adn = *(const float4*)&g_ad1[n * 4];
        // stats: edges 0..deg-1 from CSR, edge deg = self
        float M[4], S[4];
#pragma unroll
        for (int h = 0; h < 4; h++) { M[h] = -1e30f; S[h] = 0.f; }
        for (int e = lane; e <= deg; e += 32) {
            int s = (e == deg) ? n : g_csr_src[p0 + e];
            float4 as = *(const float4*)&g_as1[s * 4];
            float v[4] = { leaky(as.x + adn.x), leaky(as.y + adn.y),
                           leaky(as.z + adn.z), leaky(as.w + adn.w) };
#pragma unroll
            for (int h = 0; h < 4; h++) {
                float Mn = fmaxf(M[h], v[h]);
                S[h] = S[h] * __expf(M[h] - Mn) + __expf(v[h] - Mn);
                M[h] = Mn;
            }
        }
#pragma unroll
        for (int o = 16; o > 0; o >>= 1) {
#pragma unroll
            for (int h = 0; h < 4; h++) {
                float Mo = __shfl_xor_sync(0xffffffffu, M[h], o);
                float So = __shfl_xor_sync(0xffffffffu, S[h], o);
                float Mn = fmaxf(M[h], Mo);
                S[h] = S[h] * __expf(M[h] - Mn) + So * __expf(Mo - Mn);
                M[h] = Mn;
            }
        }
        float Sinv[4];
#pragma unroll
        for (int h = 0; h < 4; h++) Sinv[h] = 1.f / S[h];
        // accumulate z[h][k] = sum alpha_h * x[src][k]
        float z[4][16];
#pragma unroll
        for (int h = 0; h < 4; h++)
#pragma unroll
            for (int k = 0; k < 16; k++) z[h][k] = 0.f;
        for (int e = lane; e <= deg; e += 32) {
            int s = (e == deg) ? n : g_csr_src[p0 + e];
            float4 as = *(const float4*)&g_as1[s * 4];
            float al[4] = {
                __expf(leaky(as.x + adn.x) - M[0]) * Sinv[0],
                __expf(leaky(as.y + adn.y) - M[1]) * Sinv[1],
                __expf(leaky(as.z + adn.z) - M[2]) * Sinv[2],
                __expf(leaky(as.w + adn.w) - M[3]) * Sinv[3] };
            const float4* xp = (const float4*)(x + s * FIN);
            float xr[16];
#pragma unroll
            for (int q = 0; q < 4; q++) {
                float4 v = xp[q];
                xr[q * 4 + 0] = v.x; xr[q * 4 + 1] = v.y;
                xr[q * 4 + 2] = v.z; xr[q * 4 + 3] = v.w;
            }
#pragma unroll
            for (int h = 0; h < 4; h++)
#pragma unroll
                for (int k = 0; k < 16; k++) z[h][k] += al[h] * xr[k];
        }
        // butterfly-reduce 64 floats
#pragma unroll
        for (int o = 16; o > 0; o >>= 1)
#pragma unroll
            for (int h = 0; h < 4; h++)
#pragma unroll
                for (int k = 0; k < 16; k++)
                    z[h][k] += __shfl_xor_sync(0xffffffffu, z[h][k], o);
        // lanes write 2 values each
        int v0 = lane * 2, v1 = lane * 2 + 1;
        sz[i][v0] = z[v0 >> 4][v0 & 15];
        sz[i][v1] = z[v1 >> 4][v1 & 15];
    }
    __syncthreads();

    // ---- phase 2: c = column, W1 column in registers ----
    int c = t;                  // 0..511
    int h = c >> 7;
    float w1r[16];
#pragma unroll
    for (int k = 0; k < 16; k++) w1r[k] = W1[k * C1 + c];
    for (int i = 0; i < A1_NODES; i++) {
        int n = n0 + i;
        if (n >= NN) break;
        const float* zr = &sz[i][h * 16];
        float acc = 0.f;
#pragma unroll
        for (int q = 0; q < 4; q++) {
            float4 zv = *(const float4*)&zr[q * 4];
            acc += zv.x * w1r[q * 4 + 0] + zv.y * w1r[q * 4 + 1]
                 + zv.z * w1r[q * 4 + 2] + zv.w * w1r[q * 4 + 3];
        }
        g_out1h[n * C1 + c] = __float2half_rn(acc);
    }
}

// ---------------- K8: h2 = elu(out1+b1) @ W2 via WMMA, fused layer2 logits ----------------
#define AS_LD 72
#define BS_LD 136
#define CS_LD 136
__global__ void k_gemm2w(const float* __restrict__ b1, const float* __restrict__ W2,
                         const float* __restrict__ as2, const float* __restrict__ ad2) {
    __shared__ __align__(16) char sbuf[64 * CS_LD * 4];   // 34816 B, aliased
    __half (*As)[AS_LD] = (__half(*)[AS_LD])sbuf;
    __half (*Bs)[BS_LD] = (__half(*)[BS_LD])(sbuf + 64 * AS_LD * 2);
    float  (*Cs)[CS_LD] = (float(*)[CS_LD])sbuf;
    __shared__ float sb1[C1];
    __shared__ float sa[HID], sd[HID];

    int t = threadIdx.x;
    int wid = t >> 5, lane = t & 31;
    int wm = wid >> 1, wn = wid & 1;
    int row0 = blockIdx.x * 64;

    for (int i = t; i < C1; i += 256) sb1[i] = b1[i];
    if (t < HID) { sa[t] = as2[t]; sd[t] = ad2[t]; }
    __syncthreads();

    wmma::fragment<wmma::accumulator, 16, 16, 16, float> acc[4];
#pragma unroll
    for (int i = 0; i < 4; i++) wmma::fill_fragment(acc[i], 0.f);

    int r = t >> 2, cseg = t & 3;

    for (int kt = 0; kt < C1; kt += 64) {
        int row = row0 + r;
        if (row < NN) {
            const uint2* srcp = (const uint2*)&g_out1h[row * C1 + kt];
#pragma unroll
            for (int j = 0; j < 4; j++) {
                int c4 = cseg * 4 + j;
                float4 v = h4_to_f4(srcp[c4]);
                int cb = kt + c4 * 4;
                v.x = eluf(v.x + sb1[cb + 0]);
                v.y = eluf(v.y + sb1[cb + 1]);
                v.z = eluf(v.z + sb1[cb + 2]);
                v.w = eluf(v.w + sb1[cb + 3]);
                *(uint2*)&As[r][c4 * 4] = f4_to_h4(v);
            }
        } else {
            uint2 z; z.x = 0u; z.y = 0u;
#pragma unroll
            for (int j = 0; j < 4; j++) *(uint2*)&As[r][(cseg * 4 + j) * 4] = z;
        }
#pragma unroll
        for (int j = 0; j < 8; j++) {
            int idx = t + j * 256;
            int rr = idx >> 5, cc = idx & 31;
            float4 w = *(const float4*)&W2[(kt + rr) * HID + cc * 4];
            *(uint2*)&Bs[rr][cc * 4] = f4_to_h4(w);
        }
        __syncthreads();
#pragma unroll
        for (int kk = 0; kk < 4; kk++) {
            wmma::fragment<wmma::matrix_a, 16, 16, 16, __half, wmma::row_major> af;
            wmma::load_matrix_sync(af, &As[wm * 16][kk * 16], AS_LD);
#pragma unroll
            for (int nf = 0; nf < 4; nf++) {
                wmma::fragment<wmma::matrix_b, 16, 16, 16, __half, wmma::row_major> bf;
                wmma::load_matrix_sync(bf, &Bs[kk * 16][wn * 64 + nf * 16], BS_LD);
                wmma::mma_sync(acc[nf], af, bf, acc[nf]);
            }
        }
        __syncthreads();
    }
#pragma unroll
    for (int nf = 0; nf < 4; nf++)
        wmma::store_matrix_sync(&Cs[wm * 16][wn * 64 + nf * 16], acc[nf], CS_LD,
                                wmma::mem_row_major);
    __syncthreads();
    {
        int r2 = t >> 2, seg = t & 3;
        int row = row0 + r2;
        if (row < NN) {
            uint2* dstp = (uint2*)&g_h2h[row * HID];
#pragma unroll
            for (int j = 0; j < 8; j++) {
                int c4 = seg * 8 + j;
                float4 v = make_float4(Cs[r2][c4 * 4], Cs[r2][c4 * 4 + 1],
                                       Cs[r2][c4 * 4 + 2], Cs[r2][c4 * 4 + 3]);
                dstp[c4] = f4_to_h4(v);
            }
        }
    }
#pragma unroll
    for (int i = 0; i < 8; i++) {
        int rI = wid * 8 + i;
        int row = row0 + rI;
        float s = 0.f, d = 0.f;
#pragma unroll
        for (int c = 0; c < 4; c++) {
            float v = Cs[rI][lane + c * 32];
            s += v * sa[lane + c * 32];
            d += v * sd[lane + c * 32];
        }
#pragma unroll
        for (int o = 16; o > 0; o >>= 1) {
            s += __shfl_xor_sync(0xffffffffu, s, o);
            d += __shfl_xor_sync(0xffffffffu, d, o);
        }
        if (lane == 0 && row < NN) { g_as2[row] = s; g_ad2[row] = d; }
    }
}

// ---------------- K12: layer2 fused softmax + gather (warp per node) -------
__global__ void k_agg2(void) {
    __shared__ int   ssrc[4][MAXD];
    __shared__ float salpha[4][MAXD];
    int t = threadIdx.x;
    int w = t >> 5, lane = t & 31;
    int n = blockIdx.x * 4 + w;
    int p0 = g_off[n], deg = g_off[n + 1] - p0;
    int degc = min(deg, MAXD);
    for (int i = lane; i < degc; i += 32) ssrc[w][i] = g_csr_src[p0 + i];
    __syncwarp();
    float adn = g_ad2[n];
    float vself = leaky(g_as2[n] + adn);
    float M = (lane == 0) ? vself : -1e30f;
    float S = (lane == 0) ? 1.f : 0.f;
    for (int i = lane; i < deg; i += 32) {
        int s = (i < MAXD) ? ssrc[w][i] : g_csr_src[p0 + i];
        float v = leaky(g_as2[s] + adn);
        float Mn = fmaxf(M, v);
        S = S * __expf(M - Mn) + __expf(v - Mn);
        M = Mn;
    }
#pragma unroll
    for (int o = 16; o > 0; o >>= 1) {
        float Mo = __shfl_xor_sync(0xffffffffu, M, o);
        float So = __shfl_xor_sync(0xffffffffu, S, o);
        float Mn = fmaxf(M, Mo);
        S = S * __expf(M - Mn) + So * __expf(Mo - Mn);
        M = Mn;
    }
    float Sinv = 1.f / S;
    float aself = __expf(vself - M) * Sinv;
    for (int i = lane; i < degc; i += 32) {
        int s = ssrc[w][i];
        salpha[w][i] = __expf(leaky(g_as2[s] + adn) - M) * Sinv;
    }
    __syncwarp();
    const uint2* h2p = (const uint2*)g_h2h;
    float4 acc;
    {
        float4 v = h4_to_f4(h2p[n * 32 + lane]);
        acc = make_float4(aself * v.x, aself * v.y, aself * v.z, aself * v.w);
    }
    int e = 0;
    for (; e + 1 < degc; e += 2) {
        int s0 = ssrc[w][e], s1 = ssrc[w][e + 1];
        float a0 = salpha[w][e], a1 = salpha[w][e + 1];
        float4 v0 = h4_to_f4(h2p[s0 * 32 + lane]);
        float4 v1 = h4_to_f4(h2p[s1 * 32 + lane]);
        acc.x += a0 * v0.x + a1 * v1.x;
        acc.y += a0 * v0.y + a1 * v1.y;
        acc.z += a0 * v0.z + a1 * v1.z;
        acc.w += a0 * v0.w + a1 * v1.w;
    }
    for (; e < deg; e++) {
        int s; float a;
        if (e < MAXD) { s = ssrc[w][e]; a = salpha[w][e]; }
        else {
            s = g_csr_src[p0 + e];
            a = __expf(leaky(g_as2[s] + adn) - M) * Sinv;
        }
        float4 v = h4_to_f4(h2p[s * 32 + lane]);
        acc.x += a * v.x; acc.y += a * v.y; acc.z += a * v.z; acc.w += a * v.w;
    }
    ((uint2*)g_out2h)[n * 32 + lane] = f4_to_h4(acc);
}

// ---------------- K13: elu(out2+b2) + segmented mean-pool ----------------
__global__ void k_pool(const int* __restrict__ batch, const float* __restrict__ b2) {
    int c = threadIdx.x;
    int n0 = blockIdx.x * 64;
    float b2c = b2[c];
    int curg = -1;
    float acc = 0.f;
    int cnt = 0;
    for (int i = 0; i < 64; i++) {
        int n = n0 + i;
        if (n >= NN) break;
        int g = batch[n];
        if (g != curg) {
            if (curg >= 0) {
                atomicAdd(&g_pool[curg * HID + c], acc);
                if (c == 0) atomicAdd(&g_cnt[curg], (float)cnt);
            }
            curg = g; acc = 0.f; cnt = 0;
        }
        float v = __half2float(g_out2h[n * HID + c]) + b2c;
        acc += eluf(v);
        cnt++;
    }
    if (curg >= 0) {
        atomicAdd(&g_pool[curg * HID + c], acc);
        if (c == 0) atomicAdd(&g_cnt[curg], (float)cnt);
    }
}

// ---------------- K14: graph MLP + classifier ----------------
__global__ void k_final(const float* __restrict__ gfeat,
                        const float* __restrict__ Wg1, const float* __restrict__ bg1,
                        const float* __restrict__ Wg2, const float* __restrict__ bg2,
                        const float* __restrict__ Wc1, const float* __restrict__ bc1,
                        const float* __restrict__ Wc2, const float* __restrict__ bc2,
                        float* __restrict__ out) {
    int g = blockIdx.x;
    int t = threadIdx.x;
    __shared__ float z[HID + 32];
    __shared__ float hg[32];
    __shared__ float gfr[10];
    __shared__ float t1[128];
    if (t < 10) gfr[t] = gfeat[g * 10 + t];
    __syncthreads();
    if (t < 32) {
        float s = bg1[t];
#pragma unroll
        for (int k = 0; k < 10; k++) s += gfr[k] * Wg1[k * 32 + t];
        hg[t] = fmaxf(s, 0.f);
    }
    if (t < HID) {
        float inv = 1.f / fmaxf(g_cnt[g], 1.f);
        z[t] = g_pool[g * HID + t] * inv;
    }
    __syncthreads();
    if (t < 32) {
        float s = bg2[t];
#pragma unroll
        for (int k = 0; k < 32; k++) s += hg[k] * Wg2[k * 32 + t];
        z[HID + t] = s;
    }
    __syncthreads();
    if (t < 128) {
        float s = bc1[t];
        for (int k = 0; k < HID + 32; k++) s += z[k] * Wc1[k * 128 + t];
        t1[t] = fmaxf(s, 0.f);
    }
    __syncthreads();
    if (t < 6) {
        float s = bc2[t];
        for (int k = 0; k < 128; k++) s += t1[k] * Wc2[k * 6 + t];
        out[g * 6 + t] = s;
    }
}

// ---------------- launch ----------------
extern "C" void kernel_launch(void* const* d_in, const int* in_sizes, int n_in,
                              void* d_out, int out_size) {
    const float* x     = (const float*)d_in[0];
    const int*   ei    = (const int*)d_in[1];
    const int*   batch = (const int*)d_in[2];
    const float* gfeat = (const float*)d_in[3];
    const float* W1    = (const float*)d_in[4];
    const float* as1   = (const float*)d_in[5];
    const float* ad1   = (const float*)d_in[6];
    const float* b1    = (const float*)d_in[7];
    const float* W2    = (const float*)d_in[8];
    const float* as2   = (const float*)d_in[9];
    const float* ad2   = (const float*)d_in[10];
    const float* b2    = (const float*)d_in[11];
    const float* Wg1   = (const float*)d_in[12];
    const float* bg1   = (const float*)d_in[13];
    const float* Wg2   = (const float*)d_in[14];
    const float* bg2   = (const float*)d_in[15];
    const float* Wc1   = (const float*)d_in[16];
    const float* bc1   = (const float*)d_in[17];
    const float* Wc2   = (const float*)d_in[18];
    const float* bc2   = (const float*)d_in[19];
    float* out = (float*)d_out;

    const int* src = ei;
    const int* dst = ei + EE;

    k_prep<<<1, 256>>>(W1, as1, ad1);
    k_zero<<<(SCAN_PAD + 255) / 256, 256>>>();
    k_att1<<<(NN + 255) / 256, 256>>>(x);
    // CSR build
    k_hist<<<(EE + 255) / 256, 256>>>(dst);
    k_scan_block<<<SCAN_NB, 256>>>();
    k_scan_top<<<1, 256>>>();
    k_scan_add<<<(SCAN_PAD + 256) / 256, 256>>>();
    k_fill<<<(EE + 255) / 256, 256>>>(src, dst);
    // layer1: fused softmax + aggregate-then-transform
    k_agg1x<<<A1_GRID, 512>>>(x, W1);
    // layer2: WMMA gemm + fused logits
    k_gemm2w<<<(NN + 63) / 64, 256>>>(b1, W2, as2, ad2);
    k_agg2<<<NN / 4, 128>>>();
    // pool + heads
    k_pool<<<(NN + 63) / 64, 128>>>(batch, b2);
    k_final<<<GG, 160>>>(gfeat, Wg1, bg1, Wg2, bg2, Wc1, bc1, Wc2, bc2, out);
}

// round 6
// speedup vs baseline: 1.3898x; 1.3898x over previous
#include <cuda_runtime.h>
#include <cuda_fp16.h>
#include <mma.h>
#include <math.h>

using namespace nvcuda;

#define NN 50000
#define EE 400000
#define GG 64
#define FIN 16
#define HID 128
#define HEADS 4
#define C1 512   // HEADS*HID
#define MAXD 64

#define SCAN_NB 196          // ceil(50000/256)
#define SCAN_PAD (SCAN_NB*256)

// ---------------- scratch (static device memory; no allocs) ----------------
__device__ __half   g_zh[NN * 64];        // aggregated x per head (fp16)  6.4 MB
__device__ __half   g_h2h[NN * HID];      // fp16                12.8 MB
__device__ __half   g_out2h[NN * HID];    // fp16                12.8 MB
__device__ float    g_as1[NN * HEADS], g_ad1[NN * HEADS];
__device__ float    g_as2[NN], g_ad2[NN];
__device__ float    g_Ws1[FIN * HEADS], g_Wd1[FIN * HEADS];
__device__ float    g_pool[GG * HID];
__device__ float    g_cnt[GG];
// CSR by destination
__device__ int      g_deg[SCAN_PAD];
__device__ int      g_off[SCAN_PAD + 1];
__device__ int      g_cur[NN];
__device__ int      g_part[SCAN_NB];
__device__ int      g_pref[SCAN_NB];
__device__ int      g_csr_src[EE];

// ---------------- helpers ----------------
__device__ __forceinline__ float leaky(float x) { return x > 0.f ? x : 0.2f * x; }
__device__ __forceinline__ float eluf(float x)  { return x > 0.f ? x : expm1f(x); }

__device__ __forceinline__ float4 h4_to_f4(uint2 u) {
    __half2 a = *(__half2*)&u.x, b = *(__half2*)&u.y;
    float2 fa = __half22float2(a), fb = __half22float2(b);
    return make_float4(fa.x, fa.y, fb.x, fb.y);
}
__device__ __forceinline__ uint2 f4_to_h4(float4 v) {
    __half2 a = __floats2half2_rn(v.x, v.y), b = __floats2half2_rn(v.z, v.w);
    uint2 u; u.x = *(unsigned*)&a; u.y = *(unsigned*)&b; return u;
}

// ---------------- K0: fold layer1 attention vectors into W1, zero pool ----------------
__global__ void k_prep(const float* __restrict__ W1, const float* __restrict__ as1,
                       const float* __restrict__ ad1) {
    int t = threadIdx.x;
    if (t < FIN * HEADS) {
        int k = t >> 2, h = t & 3;
        float s = 0.f, d = 0.f;
        for (int c = 0; c < HID; c++) {
            float w = W1[k * C1 + h * HID + c];
            s += w * as1[h * HID + c];
            d += w * ad1[h * HID + c];
        }
        g_Ws1[t] = s; g_Wd1[t] = d;
    }
    for (int i = t; i < GG * HID; i += blockDim.x) g_pool[i] = 0.f;
    if (t < GG) g_cnt[t] = 0.f;
}

__global__ void k_zero(void) {
    int i = blockIdx.x * blockDim.x + threadIdx.x;
    if (i < SCAN_PAD) g_deg[i] = 0;
}

// ---------------- CSR build ----------------
__global__ void k_hist(const int* __restrict__ dst) {
    int e = blockIdx.x * blockDim.x + threadIdx.x;
    if (e >= EE) return;
    atomicAdd(&g_deg[dst[e]], 1);
}

__global__ void k_scan_block(void) {
    __shared__ int s[256];
    int t = threadIdx.x;
    int i = blockIdx.x * 256 + t;
    int v = g_deg[i];
    s[t] = v;
    __syncthreads();
#pragma unroll
    for (int o = 1; o < 256; o <<= 1) {
        int x = (t >= o) ? s[t - o] : 0;
        __syncthreads();
        s[t] += x;
        __syncthreads();
    }
    g_off[i] = s[t] - v;
    if (t == 255) g_part[blockIdx.x] = s[255];
}

__global__ void k_scan_top(void) {
    __shared__ int s[256];
    int t = threadIdx.x;
    int v = (t < SCAN_NB) ? g_part[t] : 0;
    s[t] = v;
    __syncthreads();
#pragma unroll
    for (int o = 1; o < 256; o <<= 1) {
        int x = (t >= o) ? s[t - o] : 0;
        __syncthreads();
        s[t] += x;
        __syncthreads();
    }
    if (t < SCAN_NB) g_pref[t] = s[t] - v;
}

__global__ void k_scan_add(void) {
    int i = blockIdx.x * blockDim.x + threadIdx.x;
    if (i > SCAN_PAD) return;
    if (i == SCAN_PAD) { g_off[i] = EE; return; }
    int p = g_off[i] + g_pref[i >> 8];
    g_off[i] = p;
    if (i < NN) g_cur[i] = p;
}

__global__ void k_fill(const int* __restrict__ src, const int* __restrict__ dst) {
    int e = blockIdx.x * blockDim.x + threadIdx.x;
    if (e >= EE) return;
    int d = dst[e];
    int p = atomicAdd(&g_cur[d], 1);
    g_csr_src[p] = src[e];
}

// ---------------- K2: per-node attention logits layer1 ----------------
__global__ void k_att1(const float* __restrict__ x) {
    __shared__ float ws[FIN * HEADS], wd[FIN * HEADS];
    int t = threadIdx.x;
    if (t < FIN * HEADS) { ws[t] = g_Ws1[t]; wd[t] = g_Wd1[t]; }
    __syncthreads();
    int n = blockIdx.x * blockDim.x + t;
    if (n >= NN) return;
    float xr[FIN];
    const float4* xp = (const float4*)(x + n * FIN);
#pragma unroll
    for (int i = 0; i < 4; i++) {
        float4 v = xp[i];
        xr[i * 4 + 0] = v.x; xr[i * 4 + 1] = v.y; xr[i * 4 + 2] = v.z; xr[i * 4 + 3] = v.w;
    }
#pragma unroll
    for (int h = 0; h < HEADS; h++) {
        float s = 0.f, d = 0.f;
#pragma unroll
        for (int k = 0; k < FIN; k++) { s += xr[k] * ws[k * 4 + h]; d += xr[k] * wd[k * 4 + h]; }
        g_as1[n * 4 + h] = s;
        g_ad1[n * 4 + h] = d;
    }
}

// ---------------- K3: layer1 softmax + x-space aggregation (thread per node-head) ----
__global__ void k_zagg(const float* __restrict__ x) {
    int tid = blockIdx.x * blockDim.x + threadIdx.x;
    int n = tid >> 2, h = tid & 3;
    if (n >= NN) return;
    int p0 = g_off[n], deg = g_off[n + 1] - p0;
    float adn = g_ad1[n * 4 + h];
    float vself = leaky(g_as1[n * 4 + h] + adn);
    // pass 1: max
    float M = vself;
    for (int e = 0; e < deg; e++) {
        int s = g_csr_src[p0 + e];
        M = fmaxf(M, leaky(g_as1[s * 4 + h] + adn));
    }
    // pass 2: exp-weights, denom, z accumulation
    float S = __expf(vself - M);
    float z[16];
    const float4* xp = (const float4*)(x + n * FIN);
#pragma unroll
    for (int q = 0; q < 4; q++) {
        float4 v = xp[q];
        z[q * 4 + 0] = S * v.x; z[q * 4 + 1] = S * v.y;
        z[q * 4 + 2] = S * v.z; z[q * 4 + 3] = S * v.w;
    }
    for (int e = 0; e < deg; e++) {
        int s = g_csr_src[p0 + e];
        float a = __expf(leaky(g_as1[s * 4 + h] + adn) - M);
        S += a;
        const float4* sp = (const float4*)(x + s * FIN);
#pragma unroll
        for (int q = 0; q < 4; q++) {
            float4 v = sp[q];
            z[q * 4 + 0] += a * v.x; z[q * 4 + 1] += a * v.y;
            z[q * 4 + 2] += a * v.z; z[q * 4 + 3] += a * v.w;
        }
    }
    float Sinv = 1.f / S;
    __half* zp = &g_zh[n * 64 + h * 16];
#pragma unroll
    for (int q = 0; q < 4; q++) {
        float4 v = make_float4(z[q * 4 + 0] * Sinv, z[q * 4 + 1] * Sinv,
                               z[q * 4 + 2] * Sinv, z[q * 4 + 3] * Sinv);
        *(uint2*)&zp[q * 4] = f4_to_h4(v);
    }
}

// ---------------- K8: fused layer1-transform + layer2 GEMM (WMMA) --------------
// Per 64-node tile, per 128-col chunk h:
//   stage1: T = z_h(64x16) @ W1_h(16x128) [K=16 MMA] -> elu(T + b1) -> fp16 As
//   stage2: acc(64x128) += As @ W2[h*128.., :]       [K=128 MMA]
// Epilogue: h2h write + layer2 attention logits.
#define F_LD 136
#define Z_LD 72
#define OFF_BS 0            // Bs (128x136 half) | Cs2/CsF (64x136 float) : 34816 B
#define OFF_AS 34816        // As 64x136 half : 17408
#define OFF_ZS 52224        // zs 64x72 half  : 9216
#define OFF_W1 61440        // w1s 16x136 half: 4352
#define OFF_B1 65792        // sb1 512 f      : 2048
#define OFF_SA 67840        // sa 128 f       : 512
#define OFF_SD 68352        // sd 128 f       : 512
#define SMEM_TOT 68864

__global__ __launch_bounds__(256) void k_fused2(
    const float* __restrict__ b1, const float* __restrict__ W1,
    const float* __restrict__ W2,
    const float* __restrict__ as2, const float* __restrict__ ad2) {
    extern __shared__ __align__(16) char smem[];
    __half* Bs  = (__half*)(smem + OFF_BS);
    float*  Cs  = (float*)(smem + OFF_BS);     // alias
    __half* As  = (__half*)(smem + OFF_AS);
    __half* zs  = (__half*)(smem + OFF_ZS);
    __half* w1s = (__half*)(smem + OFF_W1);
    float*  sb1 = (float*)(smem + OFF_B1);
    float*  sa  = (float*)(smem + OFF_SA);
    float*  sd  = (float*)(smem + OFF_SD);

    int t = threadIdx.x;
    int wid = t >> 5, lane = t & 31;
    int wm = wid >> 1, wn = wid & 1;
    int row0 = blockIdx.x * 64;

    for (int i = t; i < C1; i += 256) sb1[i] = b1[i];
    if (t < HID) { sa[t] = as2[t]; sd[t] = ad2[t]; }
    // load z tile: 64 rows x 16 uint2
    {
        uint2 zzero; zzero.x = 0u; zzero.y = 0u;
#pragma unroll
        for (int j = 0; j < 4; j++) {
            int idx = t + j * 256;            // 0..1023
            int r = idx >> 4, q = idx & 15;
            int row = row0 + r;
            uint2 v = (row < NN) ? ((const uint2*)g_zh)[row * 16 + q] : zzero;
            *(uint2*)&zs[r * Z_LD + q * 4] = v;
        }
    }

    wmma::fragment<wmma::accumulator, 16, 16, 16, float> acc[4];
#pragma unroll
    for (int i = 0; i < 4; i++) wmma::fill_fragment(acc[i], 0.f);

    for (int h = 0; h < 4; h++) {
        int kt = h * 128;
        // load W1 chunk (16 x 128) fp32 -> fp16
#pragma unroll
        for (int j = 0; j < 8; j++) {
            int idx = t + j * 256;            // 0..2047
            int r = idx >> 7, c = idx & 127;
            w1s[r * F_LD + c] = __float2half_rn(W1[r * C1 + kt + c]);
        }
        __syncthreads();   // w1s + zs visible; prior stage2 reads of Bs done
        // stage1: T = z_h @ W1_h (K=16)
        wmma::fragment<wmma::accumulator, 16, 16, 16, float> acc2[4];
        {
            wmma::fragment<wmma::matrix_a, 16, 16, 16, __half, wmma::row_major> af;
            wmma::load_matrix_sync(af, &zs[wm * 16 * Z_LD + h * 16], Z_LD);
#pragma unroll
            for (int nf = 0; nf < 4; nf++) {
                wmma::fill_fragment(acc2[nf], 0.f);
                wmma::fragment<wmma::matrix_b, 16, 16, 16, __half, wmma::row_major> bf;
                wmma::load_matrix_sync(bf, &w1s[wn * 64 + nf * 16], F_LD);
                wmma::mma_sync(acc2[nf], af, bf, acc2[nf]);
            }
        }
        // park stage1 to Cs (aliases Bs; safe after sync above)
#pragma unroll
        for (int nf = 0; nf < 4; nf++)
            wmma::store_matrix_sync(&Cs[wm * 16 * F_LD + wn * 64 + nf * 16], acc2[nf],
                                    F_LD, wmma::mem_row_major);
        __syncthreads();
        // As = elu(Cs + b1) fp16
#pragma unroll
        for (int j = 0; j < 32; j++) {
            int idx = t + j * 256;            // 0..8191
            int r = idx >> 7, c = idx & 127;
            As[r * F_LD + c] = __float2half_rn(eluf(Cs[r * F_LD + c] + sb1[kt + c]));
        }
        __syncthreads();
        // load Bs = W2 chunk (128 x 128) fp32 -> fp16 (overwrites Cs)
#pragma unroll
        for (int j = 0; j < 16; j++) {
            int idx = t + j * 256;            // float4 idx 0..4095
            int r = idx >> 5, c4 = idx & 31;
            float4 w = *(const float4*)&W2[(kt + r) * HID + c4 * 4];
            *(uint2*)&Bs[r * F_LD + c4 * 4] = f4_to_h4(w);
        }
        __syncthreads();
        // stage2: acc += As @ Bs (K=128)
#pragma unroll
        for (int kk = 0; kk < 8; kk++) {
            wmma::fragment<wmma::matrix_a, 16, 16, 16, __half, wmma::row_major> af;
            wmma::load_matrix_sync(af, &As[wm * 16 * F_LD + kk * 16], F_LD);
#pragma unroll
            for (int nf = 0; nf < 4; nf++) {
                wmma::fragment<wmma::matrix_b, 16, 16, 16, __half, wmma::row_major> bf;
                wmma::load_matrix_sync(bf, &Bs[kk * 16 * F_LD + wn * 64 + nf * 16], F_LD);
                wmma::mma_sync(acc[nf], af, bf, acc[nf]);
            }
        }
        __syncthreads();
    }
    // park final accumulators
#pragma unroll
    for (int nf = 0; nf < 4; nf++)
        wmma::store_matrix_sync(&Cs[wm * 16 * F_LD + wn * 64 + nf * 16], acc[nf],
                                F_LD, wmma::mem_row_major);
    __syncthreads();
    // epilogue A: write h2h fp16
    {
        int r2 = t >> 2, seg = t & 3;
        int row = row0 + r2;
        if (row < NN) {
            uint2* dstp = (uint2*)&g_h2h[row * HID];
#pragma unroll
            for (int j = 0; j < 8; j++) {
                int c4 = seg * 8 + j;
                float4 v = make_float4(Cs[r2 * F_LD + c4 * 4 + 0], Cs[r2 * F_LD + c4 * 4 + 1],
                                       Cs[r2 * F_LD + c4 * 4 + 2], Cs[r2 * F_LD + c4 * 4 + 3]);
                dstp[c4] = f4_to_h4(v);
            }
        }
    }
    // epilogue B: layer2 attention logits
#pragma unroll
    for (int i = 0; i < 8; i++) {
        int rI = wid * 8 + i;
        int row = row0 + rI;
        float s = 0.f, d = 0.f;
#pragma unroll
        for (int c = 0; c < 4; c++) {
            float v = Cs[rI * F_LD + lane + c * 32];
            s += v * sa[lane + c * 32];
            d += v * sd[lane + c * 32];
        }
#pragma unroll
        for (int o = 16; o > 0; o >>= 1) {
            s += __shfl_xor_sync(0xffffffffu, s, o);
            d += __shfl_xor_sync(0xffffffffu, d, o);
        }
        if (lane == 0 && row < NN) { g_as2[row] = s; g_ad2[row] = d; }
    }
}

// ---------------- K12: layer2 fused softmax + gather (warp per node) -------
__global__ void k_agg2(void) {
    __shared__ int   ssrc[4][MAXD];
    __shared__ float salpha[4][MAXD];
    int t = threadIdx.x;
    int w = t >> 5, lane = t & 31;
    int n = blockIdx.x * 4 + w;
    int p0 = g_off[n], deg = g_off[n + 1] - p0;
    int degc = min(deg, MAXD);
    for (int i = lane; i < degc; i += 32) ssrc[w][i] = g_csr_src[p0 + i];
    __syncwarp();
    float adn = g_ad2[n];
    float vself = leaky(g_as2[n] + adn);
    float M = (lane == 0) ? vself : -1e30f;
    float S = (lane == 0) ? 1.f : 0.f;
    for (int i = lane; i < deg; i += 32) {
        int s = (i < MAXD) ? ssrc[w][i] : g_csr_src[p0 + i];
        float v = leaky(g_as2[s] + adn);
        float Mn = fmaxf(M, v);
        S = S * __expf(M - Mn) + __expf(v - Mn);
        M = Mn;
    }
#pragma unroll
    for (int o = 16; o > 0; o >>= 1) {
        float Mo = __shfl_xor_sync(0xffffffffu, M, o);
        float So = __shfl_xor_sync(0xffffffffu, S, o);
        float Mn = fmaxf(M, Mo);
        S = S * __expf(M - Mn) + So * __expf(Mo - Mn);
        M = Mn;
    }
    float Sinv = 1.f / S;
    float aself = __expf(vself - M) * Sinv;
    for (int i = lane; i < degc; i += 32) {
        int s = ssrc[w][i];
        salpha[w][i] = __expf(leaky(g_as2[s] + adn) - M) * Sinv;
    }
    __syncwarp();
    const uint2* h2p = (const uint2*)g_h2h;
    float4 acc;
    {
        float4 v = h4_to_f4(h2p[n * 32 + lane]);
        acc = make_float4(aself * v.x, aself * v.y, aself * v.z, aself * v.w);
    }
    int e = 0;
    for (; e + 1 < degc; e += 2) {
        int s0 = ssrc[w][e], s1 = ssrc[w][e + 1];
        float a0 = salpha[w][e], a1 = salpha[w][e + 1];
        float4 v0 = h4_to_f4(h2p[s0 * 32 + lane]);
        float4 v1 = h4_to_f4(h2p[s1 * 32 + lane]);
        acc.x += a0 * v0.x + a1 * v1.x;
        acc.y += a0 * v0.y + a1 * v1.y;
        acc.z += a0 * v0.z + a1 * v1.z;
        acc.w += a0 * v0.w + a1 * v1.w;
    }
    for (; e < deg; e++) {
        int s; float a;
        if (e < MAXD) { s = ssrc[w][e]; a = salpha[w][e]; }
        else {
            s = g_csr_src[p0 + e];
            a = __expf(leaky(g_as2[s] + adn) - M) * Sinv;
        }
        float4 v = h4_to_f4(h2p[s * 32 + lane]);
        acc.x += a * v.x; acc.y += a * v.y; acc.z += a * v.z; acc.w += a * v.w;
    }
    ((uint2*)g_out2h)[n * 32 + lane] = f4_to_h4(acc);
}

// ---------------- K13: elu(out2+b2) + segmented mean-pool ----------------
__global__ void k_pool(const int* __restrict__ batch, const float* __restrict__ b2) {
    int c = threadIdx.x;
    int n0 = blockIdx.x * 64;
    float b2c = b2[c];
    int curg = -1;
    float acc = 0.f;
    int cnt = 0;
    for (int i = 0; i < 64; i++) {
        int n = n0 + i;
        if (n >= NN) break;
        int g = batch[n];
        if (g != curg) {
            if (curg >= 0) {
                atomicAdd(&g_pool[curg * HID + c], acc);
                if (c == 0) atomicAdd(&g_cnt[curg], (float)cnt);
            }
            curg = g; acc = 0.f; cnt = 0;
        }
        float v = __half2float(g_out2h[n * HID + c]) + b2c;
        acc += eluf(v);
        cnt++;
    }
    if (curg >= 0) {
        atomicAdd(&g_pool[curg * HID + c], acc);
        if (c == 0) atomicAdd(&g_cnt[curg], (float)cnt);
    }
}

// ---------------- K14: graph MLP + classifier ----------------
__global__ void k_final(const float* __restrict__ gfeat,
                        const float* __restrict__ Wg1, const float* __restrict__ bg1,
                        const float* __restrict__ Wg2, const float* __restrict__ bg2,
                        const float* __restrict__ Wc1, const float* __restrict__ bc1,
                        const float* __restrict__ Wc2, const float* __restrict__ bc2,
                        float* __restrict__ out) {
    int g = blockIdx.x;
    int t = threadIdx.x;
    __shared__ float z[HID + 32];
    __shared__ float hg[32];
    __shared__ float gfr[10];
    __shared__ float t1[128];
    if (t < 10) gfr[t] = gfeat[g * 10 + t];
    __syncthreads();
    if (t < 32) {
        float s = bg1[t];
#pragma unroll
        for (int k = 0; k < 10; k++) s += gfr[k] * Wg1[k * 32 + t];
        hg[t] = fmaxf(s, 0.f);
    }
    if (t < HID) {
        float inv = 1.f / fmaxf(g_cnt[g], 1.f);
        z[t] = g_pool[g * HID + t] * inv;
    }
    __syncthreads();
    if (t < 32) {
        float s = bg2[t];
#pragma unroll
        for (int k = 0; k < 32; k++) s += hg[k] * Wg2[k * 32 + t];
        z[HID + t] = s;
    }
    __syncthreads();
    if (t < 128) {
        float s = bc1[t];
        for (int k = 0; k < HID + 32; k++) s += z[k] * Wc1[k * 128 + t];
        t1[t] = fmaxf(s, 0.f);
    }
    __syncthreads();
    if (t < 6) {
        float s = bc2[t];
        for (int k = 0; k < 128; k++) s += t1[k] * Wc2[k * 6 + t];
        out[g * 6 + t] = s;
    }
}

// ---------------- launch ----------------
extern "C" void kernel_launch(void* const* d_in, const int* in_sizes, int n_in,
                              void* d_out, int out_size) {
    const float* x     = (const float*)d_in[0];
    const int*   ei    = (const int*)d_in[1];
    const int*   batch = (const int*)d_in[2];
    const float* gfeat = (const float*)d_in[3];
    const float* W1    = (const float*)d_in[4];
    const float* as1   = (const float*)d_in[5];
    const float* ad1   = (const float*)d_in[6];
    const float* b1    = (const float*)d_in[7];
    const float* W2    = (const float*)d_in[8];
    const float* as2   = (const float*)d_in[9];
    const float* ad2   = (const float*)d_in[10];
    const float* b2    = (const float*)d_in[11];
    const float* Wg1   = (const float*)d_in[12];
    const float* bg1   = (const float*)d_in[13];
    const float* Wg2   = (const float*)d_in[14];
    const float* bg2   = (const float*)d_in[15];
    const float* Wc1   = (const float*)d_in[16];
    const float* bc1   = (const float*)d_in[17];
    const float* Wc2   = (const float*)d_in[18];
    const float* bc2   = (const float*)d_in[19];
    float* out = (float*)d_out;

    const int* src = ei;
    const int* dst = ei + EE;

    cudaFuncSetAttribute(k_fused2, cudaFuncAttributeMaxDynamicSharedMemorySize, SMEM_TOT);

    k_prep<<<1, 256>>>(W1, as1, ad1);
    k_zero<<<(SCAN_PAD + 255) / 256, 256>>>();
    k_att1<<<(NN + 255) / 256, 256>>>(x);
    // CSR build
    k_hist<<<(EE + 255) / 256, 256>>>(dst);
    k_scan_block<<<SCAN_NB, 256>>>();
    k_scan_top<<<1, 256>>>();
    k_scan_add<<<(SCAN_PAD + 256) / 256, 256>>>();
    k_fill<<<(EE + 255) / 256, 256>>>(src, dst);
    // layer1: softmax + x-space aggregation
    k_zagg<<<(NN * 4 + 255) / 256, 256>>>(x);
    // fused layer1-transform + layer2 GEMM + logits
    k_fused2<<<(NN + 63) / 64, 256, SMEM_TOT>>>(b1, W1, W2, as2, ad2);
    k_agg2<<<NN / 4, 128>>>();
    // pool + heads
    k_pool<<<(NN + 63) / 64, 128>>>(batch, b2);
    k_final<<<GG, 160>>>(gfeat, Wg1, bg1, Wg2, bg2, Wc1, bc1, Wc2, bc2, out);
}

// round 7
// speedup vs baseline: 1.6782x; 1.2075x over previous
#include <cuda_runtime.h>
#include <cuda_fp16.h>
#include <mma.h>
#include <math.h>

using namespace nvcuda;

#define NN 50000
#define EE 400000
#define GG 64
#define FIN 16
#define HID 128
#define HEADS 4
#define C1 512   // HEADS*HID
#define MAXD 64

#define SCAN_NB 196          // ceil(50000/256)
#define SCAN_PAD (SCAN_NB*256)

// ---------------- scratch (static device memory; no allocs) ----------------
__device__ __half   g_zh[NN * 64];        // aggregated x per head (fp16)  6.4 MB
__device__ __half   g_h2h[NN * HID];      // fp16                12.8 MB
__device__ __half   g_out2h[NN * HID];    // fp16                12.8 MB
__device__ __half   g_w1h[FIN * C1];      // W1 fp16
__device__ __half   g_w2h[C1 * HID];      // W2 fp16
__device__ float    g_as1[NN * HEADS], g_ad1[NN * HEADS];
__device__ float    g_as2[NN], g_ad2[NN];
__device__ float    g_Ws1[FIN * HEADS], g_Wd1[FIN * HEADS];
__device__ float    g_pool[GG * HID];
__device__ float    g_cnt[GG];
// CSR by destination
__device__ int      g_deg[SCAN_PAD];
__device__ int      g_off[SCAN_PAD + 1];
__device__ int      g_cur[NN];
__device__ int      g_part[SCAN_NB];
__device__ int      g_pref[SCAN_NB];
__device__ int      g_csr_src[EE];

// ---------------- helpers ----------------
__device__ __forceinline__ float leaky(float x) { return x > 0.f ? x : 0.2f * x; }
__device__ __forceinline__ float eluf(float x)  { return x > 0.f ? x : expm1f(x); }

__device__ __forceinline__ float4 h4_to_f4(uint2 u) {
    __half2 a = *(__half2*)&u.x, b = *(__half2*)&u.y;
    float2 fa = __half22float2(a), fb = __half22float2(b);
    return make_float4(fa.x, fa.y, fb.x, fb.y);
}
__device__ __forceinline__ uint2 f4_to_h4(float4 v) {
    __half2 a = __floats2half2_rn(v.x, v.y), b = __floats2half2_rn(v.z, v.w);
    uint2 u; u.x = *(unsigned*)&a; u.y = *(unsigned*)&b; return u;
}

// ---------------- K0: fold layer1 attention vectors into W1 ----------------
__global__ void k_prep(const float* __restrict__ W1, const float* __restrict__ as1,
                       const float* __restrict__ ad1) {
    int t = threadIdx.x;
    if (t < FIN * HEADS) {
        int k = t >> 2, h = t & 3;
        float s = 0.f, d = 0.f;
        for (int c = 0; c < HID; c++) {
            float w = W1[k * C1 + h * HID + c];
            s += w * as1[h * HID + c];
            d += w * ad1[h * HID + c];
        }
        g_Ws1[t] = s; g_Wd1[t] = d;
    }
}

// ---------------- K0b: fp16 weight conversion + zeroing (grid-stride tasks) -------
__global__ void k_prepw(const float* __restrict__ W1, const float* __restrict__ W2) {
    int i = blockIdx.x * blockDim.x + threadIdx.x;
    if (i < C1 * HID) g_w2h[i] = __float2half_rn(W2[i]);
    if (i < FIN * C1) g_w1h[i] = __float2half_rn(W1[i]);
    if (i < SCAN_PAD) g_deg[i] = 0;
    if (i < GG * HID) g_pool[i] = 0.f;
    if (i < GG) g_cnt[i] = 0.f;
}

// ---------------- CSR build ----------------
__global__ void k_hist(const int* __restrict__ dst) {
    int e = blockIdx.x * blockDim.x + threadIdx.x;
    if (e >= EE) return;
    atomicAdd(&g_deg[dst[e]], 1);
}

__global__ void k_scan_block(void) {
    __shared__ int s[256];
    int t = threadIdx.x;
    int i = blockIdx.x * 256 + t;
    int v = g_deg[i];
    s[t] = v;
    __syncthreads();
#pragma unroll
    for (int o = 1; o < 256; o <<= 1) {
        int x = (t >= o) ? s[t - o] : 0;
        __syncthreads();
        s[t] += x;
        __syncthreads();
    }
    g_off[i] = s[t] - v;
    if (t == 255) g_part[blockIdx.x] = s[255];
}

__global__ void k_scan_top(void) {
    __shared__ int s[256];
    int t = threadIdx.x;
    int v = (t < SCAN_NB) ? g_part[t] : 0;
    s[t] = v;
    __syncthreads();
#pragma unroll
    for (int o = 1; o < 256; o <<= 1) {
        int x = (t >= o) ? s[t - o] : 0;
        __syncthreads();
        s[t] += x;
        __syncthreads();
    }
    if (t < SCAN_NB) g_pref[t] = s[t] - v;
}

__global__ void k_scan_add(void) {
    int i = blockIdx.x * blockDim.x + threadIdx.x;
    if (i > SCAN_PAD) return;
    if (i == SCAN_PAD) { g_off[i] = EE; return; }
    int p = g_off[i] + g_pref[i >> 8];
    g_off[i] = p;
    if (i < NN) g_cur[i] = p;
}

__global__ void k_fill(const int* __restrict__ src, const int* __restrict__ dst) {
    int e = blockIdx.x * blockDim.x + threadIdx.x;
    if (e >= EE) return;
    int d = dst[e];
    int p = atomicAdd(&g_cur[d], 1);
    g_csr_src[p] = src[e];
}

// ---------------- K2: per-node attention logits layer1 ----------------
__global__ void k_att1(const float* __restrict__ x) {
    __shared__ float ws[FIN * HEADS], wd[FIN * HEADS];
    int t = threadIdx.x;
    if (t < FIN * HEADS) { ws[t] = g_Ws1[t]; wd[t] = g_Wd1[t]; }
    __syncthreads();
    int n = blockIdx.x * blockDim.x + t;
    if (n >= NN) return;
    float xr[FIN];
    const float4* xp = (const float4*)(x + n * FIN);
#pragma unroll
    for (int i = 0; i < 4; i++) {
        float4 v = xp[i];
        xr[i * 4 + 0] = v.x; xr[i * 4 + 1] = v.y; xr[i * 4 + 2] = v.z; xr[i * 4 + 3] = v.w;
    }
#pragma unroll
    for (int h = 0; h < HEADS; h++) {
        float s = 0.f, d = 0.f;
#pragma unroll
        for (int k = 0; k < FIN; k++) { s += xr[k] * ws[k * 4 + h]; d += xr[k] * wd[k * 4 + h]; }
        g_as1[n * 4 + h] = s;
        g_ad1[n * 4 + h] = d;
    }
}

// ---------------- K3: layer1 softmax + x-space aggregation (thread per node-head) ----
__global__ void k_zagg(const float* __restrict__ x) {
    int tid = blockIdx.x * blockDim.x + threadIdx.x;
    int n = tid >> 2, h = tid & 3;
    if (n >= NN) return;
    int p0 = g_off[n], deg = g_off[n + 1] - p0;
    float adn = g_ad1[n * 4 + h];
    float vself = leaky(g_as1[n * 4 + h] + adn);
    float M = vself;
    for (int e = 0; e < deg; e++) {
        int s = g_csr_src[p0 + e];
        M = fmaxf(M, leaky(g_as1[s * 4 + h] + adn));
    }
    float S = __expf(vself - M);
    float z[16];
    const float4* xp = (const float4*)(x + n * FIN);
#pragma unroll
    for (int q = 0; q < 4; q++) {
        float4 v = xp[q];
        z[q * 4 + 0] = S * v.x; z[q * 4 + 1] = S * v.y;
        z[q * 4 + 2] = S * v.z; z[q * 4 + 3] = S * v.w;
    }
    for (int e = 0; e < deg; e++) {
        int s = g_csr_src[p0 + e];
        float a = __expf(leaky(g_as1[s * 4 + h] + adn) - M);
        S += a;
        const float4* sp = (const float4*)(x + s * FIN);
#pragma unroll
        for (int q = 0; q < 4; q++) {
            float4 v = sp[q];
            z[q * 4 + 0] += a * v.x; z[q * 4 + 1] += a * v.y;
            z[q * 4 + 2] += a * v.z; z[q * 4 + 3] += a * v.w;
        }
    }
    float Sinv = 1.f / S;
    __half* zp = &g_zh[n * 64 + h * 16];
#pragma unroll
    for (int q = 0; q < 4; q++) {
        float4 v = make_float4(z[q * 4 + 0] * Sinv, z[q * 4 + 1] * Sinv,
                               z[q * 4 + 2] * Sinv, z[q * 4 + 3] * Sinv);
        *(uint2*)&zp[q * 4] = f4_to_h4(v);
    }
}

// ---------------- K8: fused layer1-transform + layer2 GEMM (WMMA, M=128) -------
// 512 threads, 16 warps: wm=wid>>1 (0..7) rows wm*16, wn=wid&1 cols wn*64.
// Per chunk h: stage1 T=z_h@W1_h (fp16 acc -> As), elu in place, stage2 acc += As@W2_h.
#define F_LD 136
#define Z_LD 72
#define W1_LD 520
#define OFF_AS 0                     // As 128x136 half = 34816 ; Cs float alias 0..69631
#define OFF_BS 34816                 // Bs 128x136 half = 34816
#define OFF_ZS 69632                 // zs 128x72 half  = 18432
#define OFF_W1 88064                 // w1s 16x520 half = 16640
#define OFF_B1 104704                // sb1 512 f = 2048
#define OFF_SA 106752                // 512
#define OFF_SD 107264                // 512
#define SMEM_TOT 107776

__global__ __launch_bounds__(512) void k_fused2(
    const float* __restrict__ b1,
    const float* __restrict__ as2, const float* __restrict__ ad2) {
    extern __shared__ __align__(16) char smem[];
    __half* As  = (__half*)(smem + OFF_AS);
    float*  Cs  = (float*)(smem + OFF_AS);     // alias (epilogue only)
    __half* Bs  = (__half*)(smem + OFF_BS);
    __half* zs  = (__half*)(smem + OFF_ZS);
    __half* w1s = (__half*)(smem + OFF_W1);
    float*  sb1 = (float*)(smem + OFF_B1);
    float*  sa  = (float*)(smem + OFF_SA);
    float*  sd  = (float*)(smem + OFF_SD);

    int t = threadIdx.x;
    int wid = t >> 5, lane = t & 31;
    int wm = wid >> 1, wn = wid & 1;
    int row0 = blockIdx.x * 128;

    if (t < C1) sb1[t] = b1[t];
    if (t < HID) { sa[t] = as2[t]; sd[t] = ad2[t]; }
    // load full W1 fp16 (16 x 512) into padded smem
#pragma unroll
    for (int j = 0; j < 16; j++) {
        int idx = t + j * 512;           // 0..8191
        int r = idx >> 9, c = idx & 511;
        w1s[r * W1_LD + c] = g_w1h[idx];
    }
    // load z tile: 128 rows x 16 uint2
    {
        uint2 zzero; zzero.x = 0u; zzero.y = 0u;
#pragma unroll
        for (int j = 0; j < 4; j++) {
            int idx = t + j * 512;       // 0..2047
            int r = idx >> 4, q = idx & 15;
            int row = row0 + r;
            uint2 v = (row < NN) ? ((const uint2*)g_zh)[row * 16 + q] : zzero;
            *(uint2*)&zs[r * Z_LD + q * 4] = v;
        }
    }

    wmma::fragment<wmma::accumulator, 16, 16, 16, float> acc[4];
#pragma unroll
    for (int i = 0; i < 4; i++) wmma::fill_fragment(acc[i], 0.f);
    __syncthreads();

    for (int h = 0; h < 4; h++) {
        int kt = h * 128;
        // stage1: T = z_h @ W1_h, fp16 accumulate, store straight to As
        {
            wmma::fragment<wmma::matrix_a, 16, 16, 16, __half, wmma::row_major> af;
            wmma::load_matrix_sync(af, &zs[wm * 16 * Z_LD + h * 16], Z_LD);
#pragma unroll
            for (int nf = 0; nf < 4; nf++) {
                wmma::fragment<wmma::accumulator, 16, 16, 16, __half> acc2;
                wmma::fill_fragment(acc2, __float2half(0.f));
                wmma::fragment<wmma::matrix_b, 16, 16, 16, __half, wmma::row_major> bf;
                wmma::load_matrix_sync(bf, &w1s[kt + wn * 64 + nf * 16], W1_LD);
                wmma::mma_sync(acc2, af, bf, acc2);
                wmma::store_matrix_sync(&As[wm * 16 * F_LD + wn * 64 + nf * 16], acc2,
                                        F_LD, wmma::mem_row_major);
            }
        }
        // load Bs = W2 chunk (128x128) fp16
#pragma unroll
        for (int j = 0; j < 8; j++) {
            int idx = t + j * 512;           // uint2 idx 0..4095
            int r = idx >> 5, c4 = idx & 31;
            *(uint2*)&Bs[r * F_LD + c4 * 4] = ((const uint2*)g_w2h)[(kt + r) * 32 + c4];
        }
        __syncthreads();
        // elu(As + b1) in place
#pragma unroll
        for (int j = 0; j < 32; j++) {
            int idx = t + j * 512;           // 0..16383
            int r = idx >> 7, c = idx & 127;
            float v = __half2float(As[r * F_LD + c]) + sb1[kt + c];
            As[r * F_LD + c] = __float2half_rn(eluf(v));
        }
        __syncthreads();
        // stage2: acc += As @ Bs (K=128)
#pragma unroll
        for (int kk = 0; kk < 8; kk++) {
            wmma::fragment<wmma::matrix_a, 16, 16, 16, __half, wmma::row_major> af;
            wmma::load_matrix_sync(af, &As[wm * 16 * F_LD + kk * 16], F_LD);
#pragma unroll
            for (int nf = 0; nf < 4; nf++) {
                wmma::fragment<wmma::matrix_b, 16, 16, 16, __half, wmma::row_major> bf;
                wmma::load_matrix_sync(bf, &Bs[kk * 16 * F_LD + wn * 64 + nf * 16], F_LD);
                wmma::mma_sync(acc[nf], af, bf, acc[nf]);
            }
        }
        __syncthreads();
    }
    // park final accumulators to Cs (aliases As+Bs)
#pragma unroll
    for (int nf = 0; nf < 4; nf++)
        wmma::store_matrix_sync(&Cs[wm * 16 * F_LD + wn * 64 + nf * 16], acc[nf],
                                F_LD, wmma::mem_row_major);
    __syncthreads();
    // epilogue A: write h2h fp16
    {
        int r2 = t >> 2, seg = t & 3;
        int row = row0 + r2;
        if (row < NN) {
            uint2* dstp = (uint2*)&g_h2h[row * HID];
#pragma unroll
            for (int j = 0; j < 8; j++) {
                int c4 = seg * 8 + j;
                float4 v = make_float4(Cs[r2 * F_LD + c4 * 4 + 0], Cs[r2 * F_LD + c4 * 4 + 1],
                                       Cs[r2 * F_LD + c4 * 4 + 2], Cs[r2 * F_LD + c4 * 4 + 3]);
                dstp[c4] = f4_to_h4(v);
            }
        }
    }
    // epilogue B: layer2 attention logits (warp per 8 rows)
#pragma unroll
    for (int i = 0; i < 8; i++) {
        int rI = wid * 8 + i;
        int row = row0 + rI;
        float s = 0.f, d = 0.f;
#pragma unroll
        for (int c = 0; c < 4; c++) {
            float v = Cs[rI * F_LD + lane + c * 32];
            s += v * sa[lane + c * 32];
            d += v * sd[lane + c * 32];
        }
#pragma unroll
        for (int o = 16; o > 0; o >>= 1) {
            s += __shfl_xor_sync(0xffffffffu, s, o);
            d += __shfl_xor_sync(0xffffffffu, d, o);
        }
        if (lane == 0 && row < NN) { g_as2[row] = s; g_ad2[row] = d; }
    }
}

// ---------------- K12: layer2 fused softmax + gather (warp per node) -------
__global__ void k_agg2(void) {
    __shared__ int   ssrc[4][MAXD];
    __shared__ float salpha[4][MAXD];
    int t = threadIdx.x;
    int w = t >> 5, lane = t & 31;
    int n = blockIdx.x * 4 + w;
    int p0 = g_off[n], deg = g_off[n + 1] - p0;
    int degc = min(deg, MAXD);
    for (int i = lane; i < degc; i += 32) ssrc[w][i] = g_csr_src[p0 + i];
    __syncwarp();
    float adn = g_ad2[n];
    float vself = leaky(g_as2[n] + adn);
    float M = (lane == 0) ? vself : -1e30f;
    float S = (lane == 0) ? 1.f : 0.f;
    for (int i = lane; i < deg; i += 32) {
        int s = (i < MAXD) ? ssrc[w][i] : g_csr_src[p0 + i];
        float v = leaky(g_as2[s] + adn);
        float Mn = fmaxf(M, v);
        S = S * __expf(M - Mn) + __expf(v - Mn);
        M = Mn;
    }
#pragma unroll
    for (int o = 16; o > 0; o >>= 1) {
        float Mo = __shfl_xor_sync(0xffffffffu, M, o);
        float So = __shfl_xor_sync(0xffffffffu, S, o);
        float Mn = fmaxf(M, Mo);
        S = S * __expf(M - Mn) + So * __expf(Mo - Mn);
        M = Mn;
    }
    float Sinv = 1.f / S;
    float aself = __expf(vself - M) * Sinv;
    for (int i = lane; i < degc; i += 32) {
        int s = ssrc[w][i];
        salpha[w][i] = __expf(leaky(g_as2[s] + adn) - M) * Sinv;
    }
    __syncwarp();
    const uint2* h2p = (const uint2*)g_h2h;
    float4 acc;
    {
        float4 v = h4_to_f4(h2p[n * 32 + lane]);
        acc = make_float4(aself * v.x, aself * v.y, aself * v.z, aself * v.w);
    }
    int e = 0;
    for (; e + 1 < degc; e += 2) {
        int s0 = ssrc[w][e], s1 = ssrc[w][e + 1];
        float a0 = salpha[w][e], a1 = salpha[w][e + 1];
        float4 v0 = h4_to_f4(h2p[s0 * 32 + lane]);
        float4 v1 = h4_to_f4(h2p[s1 * 32 + lane]);
        acc.x += a0 * v0.x + a1 * v1.x;
        acc.y += a0 * v0.y + a1 * v1.y;
        acc.z += a0 * v0.z + a1 * v1.z;
        acc.w += a0 * v0.w + a1 * v1.w;
    }
    for (; e < deg; e++) {
        int s; float a;
        if (e < MAXD) { s = ssrc[w][e]; a = salpha[w][e]; }
        else {
            s = g_csr_src[p0 + e];
            a = __expf(leaky(g_as2[s] + adn) - M) * Sinv;
        }
        float4 v = h4_to_f4(h2p[s * 32 + lane]);
        acc.x += a * v.x; acc.y += a * v.y; acc.z += a * v.z; acc.w += a * v.w;
    }
    ((uint2*)g_out2h)[n * 32 + lane] = f4_to_h4(acc);
}

// ---------------- K13: elu(out2+b2) + segmented mean-pool ----------------
__global__ void k_pool(const int* __restrict__ batch, const float* __restrict__ b2) {
    int c = threadIdx.x;
    int n0 = blockIdx.x * 64;
    float b2c = b2[c];
    int curg = -1;
    float acc = 0.f;
    int cnt = 0;
    for (int i = 0; i < 64; i++) {
        int n = n0 + i;
        if (n >= NN) break;
        int g = batch[n];
        if (g != curg) {
            if (curg >= 0) {
                atomicAdd(&g_pool[curg * HID + c], acc);
                if (c == 0) atomicAdd(&g_cnt[curg], (float)cnt);
            }
            curg = g; acc = 0.f; cnt = 0;
        }
        float v = __half2float(g_out2h[n * HID + c]) + b2c;
        acc += eluf(v);
        cnt++;
    }
    if (curg >= 0) {
        atomicAdd(&g_pool[curg * HID + c], acc);
        if (c == 0) atomicAdd(&g_cnt[curg], (float)cnt);
    }
}

// ---------------- K14: graph MLP + classifier ----------------
__global__ void k_final(const float* __restrict__ gfeat,
                        const float* __restrict__ Wg1, const float* __restrict__ bg1,
                        const float* __restrict__ Wg2, const float* __restrict__ bg2,
                        const float* __restrict__ Wc1, const float* __restrict__ bc1,
                        const float* __restrict__ Wc2, const float* __restrict__ bc2,
                        float* __restrict__ out) {
    int g = blockIdx.x;
    int t = threadIdx.x;
    __shared__ float z[HID + 32];
    __shared__ float hg[32];
    __shared__ float gfr[10];
    __shared__ float t1[128];
    if (t < 10) gfr[t] = gfeat[g * 10 + t];
    __syncthreads();
    if (t < 32) {
        float s = bg1[t];
#pragma unroll
        for (int k = 0; k < 10; k++) s += gfr[k] * Wg1[k * 32 + t];
        hg[t] = fmaxf(s, 0.f);
    }
    if (t < HID) {
        float inv = 1.f / fmaxf(g_cnt[g], 1.f);
        z[t] = g_pool[g * HID + t] * inv;
    }
    __syncthreads();
    if (t < 32) {
        float s = bg2[t];
#pragma unroll
        for (int k = 0; k < 32; k++) s += hg[k] * Wg2[k * 32 + t];
        z[HID + t] = s;
    }
    __syncthreads();
    if (t < 128) {
        float s = bc1[t];
        for (int k = 0; k < HID + 32; k++) s += z[k] * Wc1[k * 128 + t];
        t1[t] = fmaxf(s, 0.f);
    }
    __syncthreads();
    if (t < 6) {
        float s = bc2[t];
        for (int k = 0; k < 128; k++) s += t1[k] * Wc2[k * 6 + t];
        out[g * 6 + t] = s;
    }
}

// ---------------- launch ----------------
extern "C" void kernel_launch(void* const* d_in, const int* in_sizes, int n_in,
                              void* d_out, int out_size) {
    const float* x     = (const float*)d_in[0];
    const int*   ei    = (const int*)d_in[1];
    const int*   batch = (const int*)d_in[2];
    const float* gfeat = (const float*)d_in[3];
    const float* W1    = (const float*)d_in[4];
    const float* as1   = (const float*)d_in[5];
    const float* ad1   = (const float*)d_in[6];
    const float* b1    = (const float*)d_in[7];
    const float* W2    = (const float*)d_in[8];
    const float* as2   = (const float*)d_in[9];
    const float* ad2   = (const float*)d_in[10];
    const float* b2    = (const float*)d_in[11];
    const float* Wg1   = (const float*)d_in[12];
    const float* bg1   = (const float*)d_in[13];
    const float* Wg2   = (const float*)d_in[14];
    const float* bg2   = (const float*)d_in[15];
    const float* Wc1   = (const float*)d_in[16];
    const float* bc1   = (const float*)d_in[17];
    const float* Wc2   = (const float*)d_in[18];
    const float* bc2   = (const float*)d_in[19];
    float* out = (float*)d_out;

    const int* src = ei;
    const int* dst = ei + EE;

    cudaFuncSetAttribute(k_fused2, cudaFuncAttributeMaxDynamicSharedMemorySize, SMEM_TOT);

    k_prep<<<1, 256>>>(W1, as1, ad1);
    k_prepw<<<(C1 * HID + 255) / 256, 256>>>(W1, W2);
    k_att1<<<(NN + 255) / 256, 256>>>(x);
    // CSR build
    k_hist<<<(EE + 255) / 256, 256>>>(dst);
    k_scan_block<<<SCAN_NB, 256>>>();
    k_scan_top<<<1, 256>>>();
    k_scan_add<<<(SCAN_PAD + 256) / 256, 256>>>();
    k_fill<<<(EE + 255) / 256, 256>>>(src, dst);
    // layer1: softmax + x-space aggregation
    k_zagg<<<(NN * 4 + 255) / 256, 256>>>(x);
    // fused layer1-transform + layer2 GEMM + logits
    k_fused2<<<(NN + 127) / 128, 512, SMEM_TOT>>>(b1, as2, ad2);
    k_agg2<<<NN / 4, 128>>>();
    // pool + heads
    k_pool<<<(NN + 63) / 64, 128>>>(batch, b2);
    k_final<<<GG, 160>>>(gfeat, Wg1, bg1, Wg2, bg2, Wc1, bc1, Wc2, bc2, out);
}